// round 1
// baseline (speedup 1.0000x reference)
#include <cuda_runtime.h>

// ---------------------------------------------------------------------------
// DeeperGCN: encoder GEMM -> 3x (LN/ReLU -> softmax-aggr GENConv -> MLP) -> LN -> head
// Strategy: CSR built per replay (counting sort), warp-per-dst aggregation
// (no float atomics, no segment-max needed), FMA-pipe fast exp, SIMT fp32 GEMMs
// with smem-resident weights and shfl-broadcast A rows.
// ---------------------------------------------------------------------------

#define NMAX 50048
#define EMAX 800000

__device__ int   g_is64;
__device__ int   g_src[EMAX];
__device__ int   g_dst[EMAX];
__device__ int   g_ssrc[EMAX];
__device__ int   g_deg[NMAX];
__device__ int   g_off[NMAX];
__device__ int   g_cur[NMAX];
__device__ float g_h  [NMAX * 64];
__device__ float g_z  [NMAX * 64];
__device__ float g_s  [NMAX * 64];
__device__ float g_hid[NMAX * 128];

// ---------------------------------------------------------------------------
// fast exp(m*t) on the FMA pipe: exp2(m*tl) with tl = t*log2(e).
// round-to-nearest via magic constant, degree-5 Taylor for 2^r, r in [-0.5,0.5]
// rel err ~2e-6.
// ---------------------------------------------------------------------------
__device__ __forceinline__ float fast_exp_mt(float m, float tl) {
    const float C = 12582912.0f;               // 1.5 * 2^23
    float fb = fmaf(m, tl, C);
    float nf = fb - C;
    float r  = fmaf(m, tl, -nf);
    float p  = 1.3333558146428443e-3f;
    p = fmaf(p, r, 9.6181291976956636e-3f);
    p = fmaf(p, r, 5.5504108664821580e-2f);
    p = fmaf(p, r, 2.4022650695910072e-1f);
    p = fmaf(p, r, 6.9314718055994531e-1f);
    p = fmaf(p, r, 1.0f);
    int ki = __float_as_int(fb);               // low bits hold round(m*tl)
    return __int_as_float(__float_as_int(p) + (ki << 23));
}

// ---------------------------------------------------------------------------
// Edge preprocessing
// ---------------------------------------------------------------------------
__global__ void k_detect(const int* __restrict__ w, int E) {
    int lane = threadIdx.x;
    int bad = 0;
    int lim = min(128, E);
    for (int i = lane; i < lim; i += 32) bad |= w[2 * i + 1];
    unsigned b = __ballot_sync(0xffffffffu, bad != 0);
    if (lane == 0) g_is64 = (b == 0) ? 1 : 0;
}

__global__ void k_norm(const void* __restrict__ raw, int E) {
    int e = blockIdx.x * blockDim.x + threadIdx.x;
    if (e >= E) return;
    if (g_is64) {
        const long long* p = (const long long*)raw;
        g_src[e] = (int)p[e];
        g_dst[e] = (int)p[(size_t)E + e];
    } else {
        const int* p = (const int*)raw;
        g_src[e] = p[e];
        g_dst[e] = p[(size_t)E + e];
    }
}

__global__ void k_zero(int N) {
    int i = blockIdx.x * blockDim.x + threadIdx.x;
    if (i < N) g_deg[i] = 0;
    else if (i < 2 * N) g_cur[i - N] = 0;
}

__global__ void k_count(int E) {
    int e = blockIdx.x * blockDim.x + threadIdx.x;
    if (e < E) atomicAdd(&g_deg[g_dst[e]], 1);
}

__global__ void k_scan(int n) {
    __shared__ int sm[1024];
    int t = threadIdx.x;
    int IT = (n + 1023) >> 10;
    int base = t * IT;
    int s = 0;
    for (int i = 0; i < IT; i++) { int id = base + i; if (id < n) s += g_deg[id]; }
    sm[t] = s;
    __syncthreads();
    for (int off = 1; off < 1024; off <<= 1) {
        int v = (t >= off) ? sm[t - off] : 0;
        __syncthreads();
        sm[t] += v;
        __syncthreads();
    }
    int pre = (t == 0) ? 0 : sm[t - 1];
    for (int i = 0; i < IT; i++) {
        int id = base + i;
        if (id < n) { g_off[id] = pre; pre += g_deg[id]; }
    }
}

__global__ void k_scatter(int E) {
    int e = blockIdx.x * blockDim.x + threadIdx.x;
    if (e >= E) return;
    int d = g_dst[e];
    int pos = g_off[d] + atomicAdd(&g_cur[d], 1);
    g_ssrc[pos] = g_src[e];
}

// ---------------------------------------------------------------------------
// Softmax aggregation: warp per destination node.
// s_out[d] = z[d] + (sum_j m_j*exp(m_j*t)) / (sum_j exp(m_j*t) + 1e-16)
// with m_j = relu(z[src_j]) + 1e-7  (max-subtraction omitted: identical ratio)
// ---------------------------------------------------------------------------
__global__ void k_aggr(const float* __restrict__ z, const float* __restrict__ tp,
                       int li, float* __restrict__ so, int N) {
    int w = (blockIdx.x * blockDim.x + threadIdx.x) >> 5;
    int lane = threadIdx.x & 31;
    if (w >= N) return;
    float tl = __ldg(tp + li) * 1.4426950408889634f;
    int beg = g_off[w], dg = g_deg[w];
    const float2* z2 = (const float2*)z;
    float se0 = 0.f, se1 = 0.f, sn0 = 0.f, sn1 = 0.f;
    #pragma unroll 2
    for (int j = 0; j < dg; j++) {
        int s = __ldg(&g_ssrc[beg + j]);
        float2 v = __ldg(&z2[(size_t)s * 32 + lane]);
        float m0 = fmaxf(v.x, 0.f) + 1e-7f;
        float m1 = fmaxf(v.y, 0.f) + 1e-7f;
        float e0 = fast_exp_mt(m0, tl);
        float e1 = fast_exp_mt(m1, tl);
        se0 += e0; se1 += e1;
        sn0 = fmaf(m0, e0, sn0);
        sn1 = fmaf(m1, e1, sn1);
    }
    float2 zd = __ldg(&z2[(size_t)w * 32 + lane]);
    float2 o;
    o.x = zd.x + sn0 / (se0 + 1e-16f);
    o.y = zd.y + sn1 / (se1 + 1e-16f);
    ((float2*)so)[(size_t)w * 32 + lane] = o;
}

// ---------------------------------------------------------------------------
// LayerNorm(64) + ReLU: warp per row
// ---------------------------------------------------------------------------
__global__ void k_ln64(const float* __restrict__ in, const float* __restrict__ g,
                       const float* __restrict__ b, float* __restrict__ out, int N) {
    int w = (blockIdx.x * blockDim.x + threadIdx.x) >> 5;
    int lane = threadIdx.x & 31;
    if (w >= N) return;
    float2 v = __ldg(&((const float2*)in)[(size_t)w * 32 + lane]);
    float s = v.x + v.y;
    float q = v.x * v.x + v.y * v.y;
    #pragma unroll
    for (int o = 16; o; o >>= 1) {
        s += __shfl_xor_sync(0xffffffffu, s, o);
        q += __shfl_xor_sync(0xffffffffu, q, o);
    }
    float mu = s * (1.f / 64.f);
    float var = q * (1.f / 64.f) - mu * mu;
    float rs = rsqrtf(var + 1e-5f);
    float2 gg = __ldg(&((const float2*)g)[lane]);
    float2 bb = __ldg(&((const float2*)b)[lane]);
    float2 o2;
    o2.x = fmaxf((v.x - mu) * rs * gg.x + bb.x, 0.f);
    o2.y = fmaxf((v.y - mu) * rs * gg.y + bb.y, 0.f);
    ((float2*)out)[(size_t)w * 32 + lane] = o2;
}

// ---------------------------------------------------------------------------
// GEMM [N,64] @ [64,128] + bias -> LN(128) -> ReLU  (mlp1, fused epilogue)
// 256 threads, 8 warps x 4 rows; lane owns 4 output cols; A via shfl broadcast
// ---------------------------------------------------------------------------
__global__ __launch_bounds__(256) void k_mlp1(
    const float* __restrict__ A, const float* __restrict__ W,
    const float* __restrict__ bias, const float* __restrict__ lg,
    const float* __restrict__ lb, float* __restrict__ out, int N) {
    __shared__ float Ws[64 * 128];
    __shared__ float bs[128], gs[128], lbs[128];
    int tid = threadIdx.x;
    {
        const float4* w4 = (const float4*)W;
        float4* s4 = (float4*)Ws;
        #pragma unroll
        for (int i = 0; i < 8; i++) s4[tid + i * 256] = w4[tid + i * 256];
        if (tid < 128) { bs[tid] = bias[tid]; gs[tid] = lg[tid]; lbs[tid] = lb[tid]; }
    }
    __syncthreads();
    int warp = tid >> 5, lane = tid & 31;
    int r0 = blockIdx.x * 32 + warp * 4;
    float2 a[4];
    #pragma unroll
    for (int r = 0; r < 4; r++) {
        int rr = min(r0 + r, N - 1);
        a[r] = __ldg(&((const float2*)A)[(size_t)rr * 32 + lane]);
    }
    float acc[4][4];
    #pragma unroll
    for (int r = 0; r < 4; r++)
        #pragma unroll
        for (int c = 0; c < 4; c++) acc[r][c] = 0.f;
    const float4* W4s = (const float4*)Ws;
    #pragma unroll
    for (int k = 0; k < 64; k++) {
        float4 bk = W4s[k * 32 + lane];
        #pragma unroll
        for (int r = 0; r < 4; r++) {
            float ak = __shfl_sync(0xffffffffu, (k & 1) ? a[r].y : a[r].x, k >> 1);
            acc[r][0] = fmaf(ak, bk.x, acc[r][0]);
            acc[r][1] = fmaf(ak, bk.y, acc[r][1]);
            acc[r][2] = fmaf(ak, bk.z, acc[r][2]);
            acc[r][3] = fmaf(ak, bk.w, acc[r][3]);
        }
    }
    float4 bv  = ((const float4*)bs)[lane];
    float4 gv  = ((const float4*)gs)[lane];
    float4 bbv = ((const float4*)lbs)[lane];
    #pragma unroll
    for (int r = 0; r < 4; r++) {
        int rr = r0 + r;
        float y0 = acc[r][0] + bv.x, y1 = acc[r][1] + bv.y;
        float y2 = acc[r][2] + bv.z, y3 = acc[r][3] + bv.w;
        float s = y0 + y1 + y2 + y3;
        float q = y0 * y0 + y1 * y1 + y2 * y2 + y3 * y3;
        #pragma unroll
        for (int o = 16; o; o >>= 1) {
            s += __shfl_xor_sync(0xffffffffu, s, o);
            q += __shfl_xor_sync(0xffffffffu, q, o);
        }
        float mu = s * (1.f / 128.f);
        float var = q * (1.f / 128.f) - mu * mu;
        float rs = rsqrtf(var + 1e-5f);
        float4 o4;
        o4.x = fmaxf((y0 - mu) * rs * gv.x + bbv.x, 0.f);
        o4.y = fmaxf((y1 - mu) * rs * gv.y + bbv.y, 0.f);
        o4.z = fmaxf((y2 - mu) * rs * gv.z + bbv.z, 0.f);
        o4.w = fmaxf((y3 - mu) * rs * gv.w + bbv.w, 0.f);
        if (rr < N) ((float4*)out)[(size_t)rr * 32 + lane] = o4;
    }
}

// ---------------------------------------------------------------------------
// GEMM [N,128] @ [128,64] + bias (encoder and mlp2; addmode adds into out)
// ---------------------------------------------------------------------------
__global__ __launch_bounds__(256) void k_gk128(
    const float* __restrict__ A, const float* __restrict__ W,
    const float* __restrict__ bias, float* __restrict__ out, int N, int addmode) {
    __shared__ float Ws[128 * 64];
    __shared__ float bs[64];
    int tid = threadIdx.x;
    {
        const float4* w4 = (const float4*)W;
        float4* s4 = (float4*)Ws;
        #pragma unroll
        for (int i = 0; i < 8; i++) s4[tid + i * 256] = w4[tid + i * 256];
        if (tid < 64) bs[tid] = bias[tid];
    }
    __syncthreads();
    int warp = tid >> 5, lane = tid & 31;
    int r0 = blockIdx.x * 32 + warp * 4;
    float a[4][4];
    #pragma unroll
    for (int r = 0; r < 4; r++) {
        int rr = min(r0 + r, N - 1);
        float4 t4 = __ldg(&((const float4*)A)[(size_t)rr * 32 + lane]);
        a[r][0] = t4.x; a[r][1] = t4.y; a[r][2] = t4.z; a[r][3] = t4.w;
    }
    float acc[4][2];
    #pragma unroll
    for (int r = 0; r < 4; r++) { acc[r][0] = 0.f; acc[r][1] = 0.f; }
    const float2* W2s = (const float2*)Ws;
    #pragma unroll
    for (int k = 0; k < 128; k++) {
        float2 bk = W2s[k * 32 + lane];
        #pragma unroll
        for (int r = 0; r < 4; r++) {
            float ak = __shfl_sync(0xffffffffu, a[r][k & 3], k >> 2);
            acc[r][0] = fmaf(ak, bk.x, acc[r][0]);
            acc[r][1] = fmaf(ak, bk.y, acc[r][1]);
        }
    }
    float2 bv = ((const float2*)bs)[lane];
    #pragma unroll
    for (int r = 0; r < 4; r++) {
        int rr = r0 + r;
        if (rr >= N) continue;
        float2 o2;
        o2.x = acc[r][0] + bv.x;
        o2.y = acc[r][1] + bv.y;
        if (addmode) {
            float2 h = ((float2*)out)[(size_t)rr * 32 + lane];
            o2.x += h.x; o2.y += h.y;
        }
        ((float2*)out)[(size_t)rr * 32 + lane] = o2;
    }
}

// ---------------------------------------------------------------------------
// Final: relu(LN(h)) -> d_out[0 : N*64], then head @ lin_W + lin_b -> d_out[N*64:]
// ---------------------------------------------------------------------------
__global__ void k_final(const float* __restrict__ h, const float* __restrict__ g,
                        const float* __restrict__ b, const float* __restrict__ lw,
                        const float* __restrict__ lbv, float* __restrict__ out, int N) {
    int w = (blockIdx.x * blockDim.x + threadIdx.x) >> 5;
    int lane = threadIdx.x & 31;
    if (w >= N) return;
    float2 v = __ldg(&((const float2*)h)[(size_t)w * 32 + lane]);
    float s = v.x + v.y;
    float q = v.x * v.x + v.y * v.y;
    #pragma unroll
    for (int o = 16; o; o >>= 1) {
        s += __shfl_xor_sync(0xffffffffu, s, o);
        q += __shfl_xor_sync(0xffffffffu, q, o);
    }
    float mu = s * (1.f / 64.f);
    float var = q * (1.f / 64.f) - mu * mu;
    float rs = rsqrtf(var + 1e-5f);
    float2 gg = __ldg(&((const float2*)g)[lane]);
    float2 bb = __ldg(&((const float2*)b)[lane]);
    float o0 = fmaxf((v.x - mu) * rs * gg.x + bb.x, 0.f);
    float o1 = fmaxf((v.y - mu) * rs * gg.y + bb.y, 0.f);
    float2 ov; ov.x = o0; ov.y = o1;
    ((float2*)out)[(size_t)w * 32 + lane] = ov;
    // head: 64 -> 3
    int f0 = 2 * lane, f1 = 2 * lane + 1;
    float p0 = o0 * __ldg(lw + f0 * 3 + 0) + o1 * __ldg(lw + f1 * 3 + 0);
    float p1 = o0 * __ldg(lw + f0 * 3 + 1) + o1 * __ldg(lw + f1 * 3 + 1);
    float p2 = o0 * __ldg(lw + f0 * 3 + 2) + o1 * __ldg(lw + f1 * 3 + 2);
    #pragma unroll
    for (int o = 16; o; o >>= 1) {
        p0 += __shfl_xor_sync(0xffffffffu, p0, o);
        p1 += __shfl_xor_sync(0xffffffffu, p1, o);
        p2 += __shfl_xor_sync(0xffffffffu, p2, o);
    }
    if (lane == 0) {
        size_t base = (size_t)N * 64 + (size_t)w * 3;
        out[base + 0] = p0 + __ldg(lbv + 0);
        out[base + 1] = p1 + __ldg(lbv + 1);
        out[base + 2] = p2 + __ldg(lbv + 2);
    }
}

// ---------------------------------------------------------------------------
// Host launch
// ---------------------------------------------------------------------------
extern "C" void kernel_launch(void* const* d_in, const int* in_sizes, int n_in,
                              void* d_out, int out_size) {
    const float* x    = (const float*)d_in[0];
    const void*  ei   = d_in[1];
    const float* encW = (const float*)d_in[2];
    const float* encB = (const float*)d_in[3];
    const float* t    = (const float*)d_in[4];
    const float* W1   = (const float*)d_in[5];
    const float* b1   = (const float*)d_in[6];
    const float* g1   = (const float*)d_in[7];
    const float* bb1  = (const float*)d_in[8];
    const float* W2   = (const float*)d_in[9];
    const float* b2   = (const float*)d_in[10];
    const float* ng   = (const float*)d_in[11];
    const float* nb   = (const float*)d_in[12];
    const float* lw   = (const float*)d_in[13];
    const float* lb   = (const float*)d_in[14];
    int N = in_sizes[0] / 128;
    int E = in_sizes[1] / 2;
    if (N > NMAX) N = NMAX;
    if (E > EMAX) E = EMAX;
    float* out = (float*)d_out;

    float *gh, *gz, *gs, *ghid;
    cudaGetSymbolAddress((void**)&gh,   g_h);
    cudaGetSymbolAddress((void**)&gz,   g_z);
    cudaGetSymbolAddress((void**)&gs,   g_s);
    cudaGetSymbolAddress((void**)&ghid, g_hid);

    int eb = (E + 255) / 256;
    int rowsW = (N + 7) / 8;       // warp-per-row kernels, 256 threads
    int rowsG = (N + 31) / 32;     // gemm kernels, 32 rows/block

    // edge preprocessing (CSR by dst)
    k_detect<<<1, 32>>>((const int*)ei, E);
    k_norm<<<eb, 256>>>(ei, E);
    k_zero<<<(2 * N + 255) / 256, 256>>>(N);
    k_count<<<eb, 256>>>(E);
    k_scan<<<1, 1024>>>(N);
    k_scatter<<<eb, 256>>>(E);

    // encoder
    k_gk128<<<rowsG, 256>>>(x, encW, encB, gh, N, 0);

    // 3 GENConv layers
    for (int i = 0; i < 3; i++) {
        const float* zin;
        if (i == 0) {
            zin = gh;
        } else {
            k_ln64<<<rowsW, 256>>>(gh, ng + i * 64, nb + i * 64, gz, N);
            zin = gz;
        }
        k_aggr<<<rowsW, 256>>>(zin, t, i, gs, N);
        k_mlp1<<<rowsG, 256>>>(gs, W1 + i * 8192, b1 + i * 128,
                               g1 + i * 128, bb1 + i * 128, ghid, N);
        k_gk128<<<rowsG, 256>>>(ghid, W2 + i * 8192, b2 + i * 64, gh, N, i ? 1 : 0);
    }

    // final LN + ReLU + linear head
    k_final<<<rowsW, 256>>>(gh, ng, nb, lw, lb, out, N);
}